// round 15
// baseline (speedup 1.0000x reference)
#include <cuda_runtime.h>
#include <cuda_bf16.h>
#include <math.h>
#include <stdint.h>

// ============================ device scratch ============================
__device__ float g_spart[4][256 * 256];
__device__ int   g_idxL[256];
__device__ int   g_idxR[256];
__device__ float g_xent[6144];
__device__ float g_pu[128 * 6144];
__device__ float g_pv[128 * 6144];
__device__ float g_red[24][2];
// W tiles: [q(4: nH,nL,gH,gL)][jt(12)][kt(24)] of 64j x 32k bf16 (4096B)
__device__ __align__(16) __nv_bfloat16 g_Wprep[4 * 12 * 24 * 2048];
// A tiles: [l(256)][rh(2)][kt(24)]: hi 8KB + lo 8KB (128r x 32k each)
__device__ __align__(16) __nv_bfloat16 g_Aprep[(size_t)256 * 2 * 24 * 8192];

#define NJT 12
#define NKT 24
#define NLOC 72          /* 3 jt x 24 kt per CTA */

// SMEM: 3 stages x 32KB (A hi 8K, A lo 8K, W 16K), meta 1KB, reduce 8KB
#define OFF_ST(st)  ((st) * 32768)
#define OFF_META    98304
#define OFF_SC      99328
#define SMEM_BYTES  107520

// ============================ helpers ============================
__device__ __forceinline__ uint32_t smem_u32(const void* p) {
    uint32_t a;
    asm("{ .reg .u64 t; cvta.to.shared.u64 t, %1; cvt.u32.u64 %0, t; }" : "=r"(a) : "l"(p));
    return a;
}
__device__ __forceinline__ void cp16(uint32_t s, const void* g) {
    asm volatile("cp.async.cg.shared.global [%0], [%1], 16;" :: "r"(s), "l"(g));
}
__device__ __forceinline__ void cp_commit() { asm volatile("cp.async.commit_group;"); }
__device__ __forceinline__ void cp_wait1()  { asm volatile("cp.async.wait_group 1;" ::: "memory"); }
__device__ __forceinline__ void ldsm4(uint32_t& r0, uint32_t& r1, uint32_t& r2, uint32_t& r3,
                                      uint32_t a) {
    asm volatile("ldmatrix.sync.aligned.m8n8.x4.shared.b16 {%0,%1,%2,%3}, [%4];"
                 : "=r"(r0), "=r"(r1), "=r"(r2), "=r"(r3) : "r"(a));
}
__device__ __forceinline__ void mma16816(float* d, const uint32_t* a, const uint32_t* b) {
    asm volatile("mma.sync.aligned.m16n8k16.row.col.f32.bf16.bf16.f32 "
                 "{%0,%1,%2,%3},{%4,%5,%6,%7},{%8,%9},{%0,%1,%2,%3};"
                 : "+f"(d[0]), "+f"(d[1]), "+f"(d[2]), "+f"(d[3])
                 : "r"(a[0]), "r"(a[1]), "r"(a[2]), "r"(a[3]), "r"(b[0]), "r"(b[1]));
}
__device__ __forceinline__ void split2(float d0, float d1, uint32_t& hi, uint32_t& lo) {
    union { __nv_bfloat162 b; uint32_t u; } ch, cl;
    ch.b = __floats2bfloat162_rn(d0, d1);
    float f0 = __uint_as_float(ch.u << 16);
    float f1 = __uint_as_float(ch.u & 0xFFFF0000u);
    cl.b = __floats2bfloat162_rn(d0 - f0, d1 - f1);
    hi = ch.u; lo = cl.u;
}

// ============================ Kernel P: merged weight prep + A prebuild ============================
__global__ __launch_bounds__(256) void prep_all(const float* __restrict__ Wn,
                                                const float* __restrict__ Wg,
                                                const float* __restrict__ L,
                                                const float* __restrict__ R)
{
    const int t = threadIdx.x;
    if (blockIdx.x < 576) {
        int tid = blockIdx.x * 256 + t;             // 147456 = 2*96*768
        int mat = tid / 73728;
        int rem = tid - mat * 73728;
        int kc  = rem / 768;                         // 0..95, k0 = kc*8
        int j   = rem - kc * 768;
        const float* W = mat ? Wg : Wn;
        int k0 = kc * 8;
        uint32_t hi[4], lo[4];
        #pragma unroll
        for (int p = 0; p < 4; ++p)
            split2(W[(size_t)(k0 + 2 * p) * 768 + j], W[(size_t)(k0 + 2 * p + 1) * 768 + j],
                   hi[p], lo[p]);
        int kt = kc >> 2, c = kc & 3;
        int jt = j >> 6, row = j & 63;
        int off = row * 64 + ((c ^ ((row >> 1) & 3)) << 4);
        char* bh = (char*)g_Wprep + (size_t)(((mat * 2 + 0) * NJT + jt) * NKT + kt) * 4096 + off;
        char* bl = (char*)g_Wprep + (size_t)(((mat * 2 + 1) * NJT + jt) * NKT + kt) * 4096 + off;
        *(uint4*)bh = make_uint4(hi[0], hi[1], hi[2], hi[3]);
        *(uint4*)bl = make_uint4(lo[0], lo[1], lo[2], lo[3]);
    } else {
        const int bb = blockIdx.x - 576;
        const int l = bb >> 3;
        const int ktg = bb & 7;                     // 3 kt per block
        const int rh = t >> 7, row = t & 127;
        const float* Lrow = L + (size_t)l * 768;
        #pragma unroll
        for (int kk = 0; kk < 3; ++kk) {
            const int kt = ktg * 3 + kk;
            const int k0 = kt * 32;
            const float* Rr = R + (size_t)t * 768 + k0;
            const float* Lr = Lrow + k0;
            char* base = (char*)g_Aprep + (size_t)((l * 2 + rh) * 24 + kt) * 16384;
            #pragma unroll
            for (int c = 0; c < 4; ++c) {
                float4 r0 = *(const float4*)(Rr + c * 8);
                float4 r1 = *(const float4*)(Rr + c * 8 + 4);
                float4 l0 = *(const float4*)(Lr + c * 8);
                float4 l1 = *(const float4*)(Lr + c * 8 + 4);
                uint32_t h0, h1, h2, h3, e0, e1, e2, e3;
                split2(fabsf(l0.x - r0.x), fabsf(l0.y - r0.y), h0, e0);
                split2(fabsf(l0.z - r0.z), fabsf(l0.w - r0.w), h1, e1);
                split2(fabsf(l1.x - r1.x), fabsf(l1.y - r1.y), h2, e2);
                split2(fabsf(l1.z - r1.z), fabsf(l1.w - r1.w), h3, e3);
                const int off = row * 64 + ((c ^ ((row >> 1) & 3)) << 4);
                *(uint4*)(base + off) = make_uint4(h0, h1, h2, h3);
                *(uint4*)(base + 8192 + off) = make_uint4(e0, e1, e2, e3);
            }
        }
    }
}

// ============================ Kernel A: HMMA score GEMM ============================
__device__ __forceinline__ void copy_tile(uint32_t sb, int lrh, int jt, int kt,
                                          int st, int t)
{
    const char* ga = (const char*)g_Aprep + (size_t)(lrh * 24 + kt) * 16384;
    #pragma unroll
    for (int q = 0; q < 4; ++q)
        cp16(sb + OFF_ST(st) + q * 4096 + t * 16, ga + q * 4096 + t * 16);
    #pragma unroll
    for (int q = 0; q < 4; ++q)
        cp16(sb + OFF_ST(st) + 16384 + q * 4096 + t * 16,
             (const char*)g_Wprep + (size_t)((q * NJT + jt) * NKT + kt) * 4096 + t * 16);
}

__device__ __forceinline__ void ldB(uint32_t stb, int s, int lane, int wn,
                                    uint32_t Bf[4][2][2])
{
    const int row = wn * 16 + ((lane >> 4) & 1) * 8 + (lane & 7);
    const int chunk = s * 2 + ((lane >> 3) & 1);
    const uint32_t off = row * 64 + ((chunk ^ ((row >> 1) & 3)) << 4);
    #pragma unroll
    for (int q = 0; q < 4; ++q)
        ldsm4(Bf[q][0][0], Bf[q][0][1], Bf[q][1][0], Bf[q][1][1],
              stb + 16384 + q * 4096 + off);
}
__device__ __forceinline__ void ldA(uint32_t stb, int s, int mt, int lane, int wm,
                                    uint32_t* A8)
{
    const int row = wm * 64 + mt * 16 + ((lane >> 3) & 1) * 8 + (lane & 7);
    const int chunk = s * 2 + ((lane >> 4) & 1);
    const uint32_t swz = row * 64 + ((chunk ^ ((row >> 1) & 3)) << 4);
    ldsm4(A8[0], A8[1], A8[2], A8[3], stb + swz);
    ldsm4(A8[4], A8[5], A8[6], A8[7], stb + 8192 + swz);
}

// grid 2048: b = (l<<3) | (rh<<2) | jg ; each CTA does 3 j-tiles x 24 k-tiles.
__global__ __launch_bounds__(256, 2) void score_kernel(
    const float* __restrict__ L, const float* __restrict__ R,
    const float* __restrict__ bn, const float* __restrict__ bg,
    const float* __restrict__ Wl)
{
    extern __shared__ __align__(1024) char smem[];
    const uint32_t sb = smem_u32(smem);
    const int t = threadIdx.x;
    const int lane = t & 31;
    const int wid = t >> 5;
    const int wm = wid >> 2, wn = wid & 3;          // 2m x 4n warps
    const int b = blockIdx.x;
    const int bl = b >> 3;                          // l
    const int rh = (b >> 2) & 1;                    // r half
    const int jg = b & 3;                           // j group (3 jt)
    const int lrh = bl * 2 + rh;
    const float* Lrow = L + (size_t)bl * 768;

    copy_tile(sb, lrh, jg * 3, 0, 0, t); cp_commit();
    copy_tile(sb, lrh, jg * 3, 1, 1, t); cp_commit();

    float scoreAcc[4][2] = {};

    for (int jl = 0; jl < 3; ++jl) {
        const int jt = jg * 3 + jl;
        float Uacc[4][2][4] = {};
        float Vacc[4][2][4] = {};
        __syncthreads();                             // previous epilogue done
        if (t < 64) {
            float* sm = (float*)(smem + OFF_META);
            int j = jt * 64 + t;
            sm[t] = bn[j]; sm[64 + t] = bg[j]; sm[128 + t] = Wl[j]; sm[192 + t] = Lrow[j];
        }
        for (int kt = 0; kt < NKT; ++kt) {
            const int i = jl * NKT + kt;
            const int st = i % 3;
            cp_wait1();
            __syncthreads();
            const uint32_t stb = sb + OFF_ST(st);

            // load ALL B fragments for this k-tile (both k16 steps) up front
            uint32_t Bf[2][4][2][2];
            ldB(stb, 0, lane, wn, Bf[0]);
            ldB(stb, 1, lane, wn, Bf[1]);

            if (i + 2 < NLOC) {
                const int i2 = i + 2;
                copy_tile(sb, lrh, jg * 3 + i2 / NKT, i2 % NKT, i2 % 3, t);
            }
            cp_commit();

            #pragma unroll
            for (int s = 0; s < 2; ++s) {
                #pragma unroll
                for (int mt = 0; mt < 4; ++mt) {
                    uint32_t A8[8];
                    ldA(stb, s, mt, lane, wm, A8);
                    #pragma unroll
                    for (int nt = 0; nt < 2; ++nt) {
                        mma16816(Uacc[mt][nt], A8,     Bf[s][0][nt]);
                        mma16816(Uacc[mt][nt], A8,     Bf[s][1][nt]);
                        mma16816(Vacc[mt][nt], A8,     Bf[s][2][nt]);
                        mma16816(Vacc[mt][nt], A8,     Bf[s][3][nt]);
                        mma16816(Uacc[mt][nt], A8 + 4, Bf[s][0][nt]);
                        mma16816(Vacc[mt][nt], A8 + 4, Bf[s][2][nt]);
                    }
                }
            }
            if (kt == NKT - 1) {
                const float* smf = (const float*)(smem + OFF_META);
                #pragma unroll
                for (int mt = 0; mt < 4; ++mt) {
                    #pragma unroll
                    for (int hf = 0; hf < 2; ++hf) {
                        const int r = rh * 128 + wm * 64 + mt * 16 + hf * 8 + (lane >> 2);
                        const float* Rr = R + (size_t)r * 768 + jt * 64;
                        float sc = scoreAcc[mt][hf];
                        #pragma unroll
                        for (int nt = 0; nt < 2; ++nt) {
                            #pragma unroll
                            for (int e = 0; e < 2; ++e) {
                                const int jl2 = wn * 16 + nt * 8 + ((lane & 3) << 1) + e;
                                const float x = fabsf(smf[192 + jl2] - Rr[jl2]);
                                const float u = Uacc[mt][nt][hf * 2 + e] + smf[jl2];
                                const float v = Vacc[mt][nt][hf * 2 + e] + smf[64 + jl2];
                                const float g = 1.f / (1.f + __expf(-v));
                                sc += (fmaxf(u, 0.f) * g + (1.f - g) * x) * smf[128 + jl2];
                            }
                        }
                        scoreAcc[mt][hf] = sc;
                    }
                }
            }
        }
    }

    float* sS = (float*)(smem + OFF_SC);
    __syncthreads();
    #pragma unroll
    for (int mt = 0; mt < 4; ++mt)
        #pragma unroll
        for (int hf = 0; hf < 2; ++hf)
            sS[(wm * 64 + mt * 16 + hf * 8 + (lane >> 2)) * 16 + wn * 4 + (lane & 3)] =
                scoreAcc[mt][hf];
    __syncthreads();
    if (t < 128) {
        float s = 0.f;
        #pragma unroll
        for (int q = 0; q < 16; ++q) s += sS[t * 16 + q];
        g_spart[jg][bl * 256 + rh * 128 + t] = s;
    }
}

// ============================ Kernel B: argmax (sums 4 j-group partials) ============================
__global__ __launch_bounds__(256) void argmax_kernel()
{
    const int b = blockIdx.x;
    const int t = threadIdx.x;
    const bool col = (b >= 256);
    const int idx = col ? (b - 256) : b;
    const int e = col ? (t * 256 + idx) : (idx * 256 + t);
    float v = g_spart[0][e] + g_spart[1][e] + g_spart[2][e] + g_spart[3][e];
    __shared__ float sv[256];
    __shared__ int   si[256];
    sv[t] = v; si[t] = t;
    __syncthreads();
    for (int s = 128; s > 0; s >>= 1) {
        if (t < s) {
            if (sv[t + s] > sv[t] || (sv[t + s] == sv[t] && si[t + s] < si[t])) {
                sv[t] = sv[t + s]; si[t] = si[t + s];
            }
        }
        __syncthreads();
    }
    if (t == 0) { if (col) g_idxR[idx] = si[0]; else g_idxL[idx] = si[0]; }
}

// ============================ Kernel C: attribute matching (8 blocks, warp-parallel reduce) ============================
__global__ __launch_bounds__(256) void attr_kernel(
    const float* __restrict__ L, const float* __restrict__ R,
    const float* __restrict__ AEl, const float* __restrict__ AEr,
    const float* __restrict__ empty,
    const int* __restrict__ lensL, const int* __restrict__ lensR)
{
    const int b = blockIdx.x;                        // 0..7
    const int side = b >> 2;
    const int a = b & 3;
    const float* T  = side ? R : L;
    const float* O  = side ? L : R;
    const int*   ix = side ? g_idxR : g_idxL;
    const float* AE = side ? AEr : AEl;
    const int* lens = side ? lensR : lensL;
    const int t = threadIdx.x, wid = t >> 5, lane = t & 31;

    int start = 0;
    for (int i = 0; i < a; ++i) start += lens[i];
    const int len = lens[a];
    float* rep = g_xent + (size_t)(side * 4 + a) * 768;

    if (len == 0) {
        for (int d = t; d < 768; d += 256) rep[d] = empty[d];
        return;
    }
    __shared__ float sw[256];
    __shared__ float red[256];
    __shared__ float racc[8][768];                   // per-warp accumulators

    // phase 1: warp-per-token coalesced dots
    const float* ae = AE + (size_t)a * 768;
    for (int i = wid; i < len; i += 8) {
        const float* tok = T + (size_t)(start + i) * 768;
        float acc = 0.f;
        #pragma unroll 4
        for (int d = lane; d < 768; d += 32) acc = fmaf(tok[d], ae[d], acc);
        #pragma unroll
        for (int o = 16; o > 0; o >>= 1) acc += __shfl_xor_sync(0xFFFFFFFF, acc, o);
        if (lane == 0) sw[i] = acc;
    }
    // zero per-warp accumulators (each warp its own row)
    for (int d = lane; d < 768; d += 32) racc[wid][d] = 0.f;
    __syncthreads();
    // phase 2: softmax over len
    float s = (t < len) ? sw[t] : -1e30f;
    red[t] = s;
    __syncthreads();
    for (int st = 128; st > 0; st >>= 1) {
        if (t < st) red[t] = fmaxf(red[t], red[t + st]);
        __syncthreads();
    }
    const float m = red[0];
    __syncthreads();
    const float e = (t < len) ? __expf(s - m) : 0.f;
    red[t] = e;
    __syncthreads();
    for (int st = 128; st > 0; st >>= 1) {
        if (t < st) red[t] += red[t + st];
        __syncthreads();
    }
    const float z = red[0];
    __syncthreads();
    sw[t] = e / z;
    __syncthreads();
    // phase 3: warp-per-token weighted abs-diff accumulation (coalesced)
    for (int i = wid; i < len; i += 8) {
        const int tok = start + i;
        const float w = sw[i];
        const float* Tr = T + (size_t)tok * 768;
        const float* Or = O + (size_t)ix[tok] * 768;
        #pragma unroll 4
        for (int d = lane; d < 768; d += 32)
            racc[wid][d] = fmaf(w, fabsf(Tr[d] - Or[d]), racc[wid][d]);
    }
    __syncthreads();
    // reduce 8 warp rows
    for (int d = t; d < 768; d += 256) {
        float acc = 0.f;
        #pragma unroll
        for (int w = 0; w < 8; ++w) acc += racc[w][d];
        rep[d] = acc;
    }
}

// ============================ Kernel D: entity matvec partials (float4, 128 splits) ============================
__global__ __launch_bounds__(256) void ent_partial(
    const float* __restrict__ Wn, const float* __restrict__ Wg)
{
    const int j0 = (blockIdx.x * 256 + threadIdx.x) * 4;   // grid.x = 6
    const int rs = blockIdx.y;                              // 0..127
    const int i0 = rs * 48;
    float4 au = make_float4(0.f, 0.f, 0.f, 0.f);
    float4 av = make_float4(0.f, 0.f, 0.f, 0.f);
    #pragma unroll 4
    for (int i = 0; i < 48; ++i) {
        const float xi = g_xent[i0 + i];
        const float4 wn = *(const float4*)(Wn + (size_t)(i0 + i) * 6144 + j0);
        const float4 wg = *(const float4*)(Wg + (size_t)(i0 + i) * 6144 + j0);
        au.x = fmaf(xi, wn.x, au.x); au.y = fmaf(xi, wn.y, au.y);
        au.z = fmaf(xi, wn.z, au.z); au.w = fmaf(xi, wn.w, au.w);
        av.x = fmaf(xi, wg.x, av.x); av.y = fmaf(xi, wg.y, av.y);
        av.z = fmaf(xi, wg.z, av.z); av.w = fmaf(xi, wg.w, av.w);
    }
    *(float4*)(g_pu + rs * 6144 + j0) = au;
    *(float4*)(g_pv + rs * 6144 + j0) = av;
}

// ============================ Kernel E1: entity finalize partials (24 blocks) ============================
__global__ __launch_bounds__(256) void ent_final1(
    const float* __restrict__ bn, const float* __restrict__ bg,
    const float* __restrict__ Wl2)
{
    const int t = threadIdx.x;
    const int j = blockIdx.x * 256 + t;              // 6144 total
    float u = bn[j], v = bg[j];
    #pragma unroll 8
    for (int s = 0; s < 128; ++s) { u += g_pu[s * 6144 + j]; v += g_pv[s * 6144 + j]; }
    const float x = g_xent[j];
    const float g = 1.f / (1.f + __expf(-v));
    const float hw = fmaxf(u, 0.f) * g + (1.f - g) * x;
    float l0 = hw * Wl2[(size_t)j * 2 + 0];
    float l1 = hw * Wl2[(size_t)j * 2 + 1];
    __shared__ float r0[256], r1[256];
    r0[t] = l0; r1[t] = l1;
    __syncthreads();
    for (int s = 128; s > 0; s >>= 1) {
        if (t < s) { r0[t] += r0[t + s]; r1[t] += r1[t + s]; }
        __syncthreads();
    }
    if (t == 0) { g_red[blockIdx.x][0] = r0[0]; g_red[blockIdx.x][1] = r1[0]; }
}

// ============================ Kernel E2: final softmax ============================
__global__ __launch_bounds__(32) void ent_final2(
    const float* __restrict__ bl2, float* __restrict__ out)
{
    const int t = threadIdx.x;
    float l0 = (t < 24) ? g_red[t][0] : 0.f;
    float l1 = (t < 24) ? g_red[t][1] : 0.f;
    #pragma unroll
    for (int o = 16; o > 0; o >>= 1) {
        l0 += __shfl_xor_sync(0xFFFFFFFF, l0, o);
        l1 += __shfl_xor_sync(0xFFFFFFFF, l1, o);
    }
    if (t == 0) {
        const float a = l0 + bl2[0];
        const float b = l1 + bl2[1];
        const float m = fmaxf(a, b);
        const float ea = __expf(a - m), eb = __expf(b - m);
        const float inv = 1.f / (ea + eb);
        out[0] = ea * inv;
        out[1] = eb * inv;
    }
}

// ============================ launcher ============================
extern "C" void kernel_launch(void* const* d_in, const int* in_sizes, int n_in,
                              void* d_out, int out_size)
{
    const float* left_emb   = (const float*)d_in[0];
    const float* right_emb  = (const float*)d_in[1];
    const float* Wn_tok     = (const float*)d_in[2];
    const float* bn_tok     = (const float*)d_in[3];
    const float* Wg_tok     = (const float*)d_in[4];
    const float* bg_tok     = (const float*)d_in[5];
    const float* W_lin_tok  = (const float*)d_in[6];
    const float* attr_l     = (const float*)d_in[8];
    const float* attr_r     = (const float*)d_in[9];
    const float* Wn_ent     = (const float*)d_in[10];
    const float* bn_ent     = (const float*)d_in[11];
    const float* Wg_ent     = (const float*)d_in[12];
    const float* bg_ent     = (const float*)d_in[13];
    const float* W_lin_ent  = (const float*)d_in[14];
    const float* b_lin_ent  = (const float*)d_in[15];
    const float* empty_attr = (const float*)d_in[16];
    const int*   lensL      = (const int*)d_in[17];
    const int*   lensR      = (const int*)d_in[18];
    float* out = (float*)d_out;

    cudaFuncSetAttribute(score_kernel, cudaFuncAttributeMaxDynamicSharedMemorySize, SMEM_BYTES);

    prep_all<<<2624, 256>>>(Wn_tok, Wg_tok, left_emb, right_emb);   // launch 0
    score_kernel<<<2048, 256, SMEM_BYTES>>>(left_emb, right_emb, bn_tok, bg_tok, W_lin_tok); // 1
    argmax_kernel<<<512, 256>>>();                                  // launch 2
    attr_kernel<<<8, 256>>>(left_emb, right_emb, attr_l, attr_r,
                            empty_attr, lensL, lensR);              // launch 3 (profiled)
    dim3 gridD(6, 128);
    ent_partial<<<gridD, 256>>>(Wn_ent, Wg_ent);
    ent_final1<<<24, 256>>>(bn_ent, bg_ent, W_lin_ent);
    ent_final2<<<1, 32>>>(b_lin_ent, out);
}

// round 16
// speedup vs baseline: 1.0647x; 1.0647x over previous
#include <cuda_runtime.h>
#include <cuda_bf16.h>
#include <math.h>
#include <stdint.h>

// ============================ device scratch ============================
__device__ float g_spart[4][256 * 256];
__device__ int   g_idxL[256];
__device__ int   g_idxR[256];
__device__ float g_xent[6144];
__device__ float g_attrs[8][256];
__device__ float g_pu[128 * 6144];
__device__ float g_pv[128 * 6144];
__device__ float g_red[24][2];
// W tiles: [q(4: nH,nL,gH,gL)][jt(12)][kt(24)] of 64j x 32k bf16 (4096B)
__device__ __align__(16) __nv_bfloat16 g_Wprep[4 * 12 * 24 * 2048];
// A tiles: [l(256)][rh(2)][kt(24)]: hi 8KB + lo 8KB (128r x 32k each)
__device__ __align__(16) __nv_bfloat16 g_Aprep[(size_t)256 * 2 * 24 * 8192];

#define NJT 12
#define NKT 24
#define NLOC 72          /* 3 jt x 24 kt per CTA */

// SMEM: 3 stages x 32KB (A hi 8K, A lo 8K, W 16K), meta 1KB, reduce 8KB
#define OFF_ST(st)  ((st) * 32768)
#define OFF_META    98304
#define OFF_SC      99328
#define SMEM_BYTES  107520

// ============================ helpers ============================
__device__ __forceinline__ uint32_t smem_u32(const void* p) {
    uint32_t a;
    asm("{ .reg .u64 t; cvta.to.shared.u64 t, %1; cvt.u32.u64 %0, t; }" : "=r"(a) : "l"(p));
    return a;
}
__device__ __forceinline__ void cp16(uint32_t s, const void* g) {
    asm volatile("cp.async.cg.shared.global [%0], [%1], 16;" :: "r"(s), "l"(g));
}
__device__ __forceinline__ void cp_commit() { asm volatile("cp.async.commit_group;"); }
__device__ __forceinline__ void cp_wait1()  { asm volatile("cp.async.wait_group 1;" ::: "memory"); }
__device__ __forceinline__ void ldsm4(uint32_t& r0, uint32_t& r1, uint32_t& r2, uint32_t& r3,
                                      uint32_t a) {
    asm volatile("ldmatrix.sync.aligned.m8n8.x4.shared.b16 {%0,%1,%2,%3}, [%4];"
                 : "=r"(r0), "=r"(r1), "=r"(r2), "=r"(r3) : "r"(a));
}
__device__ __forceinline__ void mma16816(float* d, const uint32_t* a, const uint32_t* b) {
    asm volatile("mma.sync.aligned.m16n8k16.row.col.f32.bf16.bf16.f32 "
                 "{%0,%1,%2,%3},{%4,%5,%6,%7},{%8,%9},{%0,%1,%2,%3};"
                 : "+f"(d[0]), "+f"(d[1]), "+f"(d[2]), "+f"(d[3])
                 : "r"(a[0]), "r"(a[1]), "r"(a[2]), "r"(a[3]), "r"(b[0]), "r"(b[1]));
}
__device__ __forceinline__ void split2(float d0, float d1, uint32_t& hi, uint32_t& lo) {
    union { __nv_bfloat162 b; uint32_t u; } ch, cl;
    ch.b = __floats2bfloat162_rn(d0, d1);
    float f0 = __uint_as_float(ch.u << 16);
    float f1 = __uint_as_float(ch.u & 0xFFFF0000u);
    cl.b = __floats2bfloat162_rn(d0 - f0, d1 - f1);
    hi = ch.u; lo = cl.u;
}

// ============================ Kernel P: merged weight prep + A prebuild ============================
__global__ __launch_bounds__(256) void prep_all(const float* __restrict__ Wn,
                                                const float* __restrict__ Wg,
                                                const float* __restrict__ L,
                                                const float* __restrict__ R)
{
    const int t = threadIdx.x;
    if (blockIdx.x < 576) {
        int tid = blockIdx.x * 256 + t;             // 147456 = 2*96*768
        int mat = tid / 73728;
        int rem = tid - mat * 73728;
        int kc  = rem / 768;                         // 0..95, k0 = kc*8
        int j   = rem - kc * 768;
        const float* W = mat ? Wg : Wn;
        int k0 = kc * 8;
        uint32_t hi[4], lo[4];
        #pragma unroll
        for (int p = 0; p < 4; ++p)
            split2(W[(size_t)(k0 + 2 * p) * 768 + j], W[(size_t)(k0 + 2 * p + 1) * 768 + j],
                   hi[p], lo[p]);
        int kt = kc >> 2, c = kc & 3;
        int jt = j >> 6, row = j & 63;
        int off = row * 64 + ((c ^ ((row >> 1) & 3)) << 4);
        char* bh = (char*)g_Wprep + (size_t)(((mat * 2 + 0) * NJT + jt) * NKT + kt) * 4096 + off;
        char* bl = (char*)g_Wprep + (size_t)(((mat * 2 + 1) * NJT + jt) * NKT + kt) * 4096 + off;
        *(uint4*)bh = make_uint4(hi[0], hi[1], hi[2], hi[3]);
        *(uint4*)bl = make_uint4(lo[0], lo[1], lo[2], lo[3]);
    } else {
        const int bb = blockIdx.x - 576;
        const int l = bb >> 3;
        const int ktg = bb & 7;                     // 3 kt per block
        const int rh = t >> 7, row = t & 127;
        const float* Lrow = L + (size_t)l * 768;
        #pragma unroll
        for (int kk = 0; kk < 3; ++kk) {
            const int kt = ktg * 3 + kk;
            const int k0 = kt * 32;
            const float* Rr = R + (size_t)t * 768 + k0;
            const float* Lr = Lrow + k0;
            char* base = (char*)g_Aprep + (size_t)((l * 2 + rh) * 24 + kt) * 16384;
            #pragma unroll
            for (int c = 0; c < 4; ++c) {
                float4 r0 = *(const float4*)(Rr + c * 8);
                float4 r1 = *(const float4*)(Rr + c * 8 + 4);
                float4 l0 = *(const float4*)(Lr + c * 8);
                float4 l1 = *(const float4*)(Lr + c * 8 + 4);
                uint32_t h0, h1, h2, h3, e0, e1, e2, e3;
                split2(fabsf(l0.x - r0.x), fabsf(l0.y - r0.y), h0, e0);
                split2(fabsf(l0.z - r0.z), fabsf(l0.w - r0.w), h1, e1);
                split2(fabsf(l1.x - r1.x), fabsf(l1.y - r1.y), h2, e2);
                split2(fabsf(l1.z - r1.z), fabsf(l1.w - r1.w), h3, e3);
                const int off = row * 64 + ((c ^ ((row >> 1) & 3)) << 4);
                *(uint4*)(base + off) = make_uint4(h0, h1, h2, h3);
                *(uint4*)(base + 8192 + off) = make_uint4(e0, e1, e2, e3);
            }
        }
    }
}

// ============================ Kernel A: HMMA score GEMM ============================
__device__ __forceinline__ void copy_tile(uint32_t sb, int lrh, int jt, int kt,
                                          int st, int t)
{
    const char* ga = (const char*)g_Aprep + (size_t)(lrh * 24 + kt) * 16384;
    #pragma unroll
    for (int q = 0; q < 4; ++q)
        cp16(sb + OFF_ST(st) + q * 4096 + t * 16, ga + q * 4096 + t * 16);
    #pragma unroll
    for (int q = 0; q < 4; ++q)
        cp16(sb + OFF_ST(st) + 16384 + q * 4096 + t * 16,
             (const char*)g_Wprep + (size_t)((q * NJT + jt) * NKT + kt) * 4096 + t * 16);
}

__device__ __forceinline__ void ldB(uint32_t stb, int s, int lane, int wn,
                                    uint32_t Bf[4][2][2])
{
    const int row = wn * 16 + ((lane >> 4) & 1) * 8 + (lane & 7);
    const int chunk = s * 2 + ((lane >> 3) & 1);
    const uint32_t off = row * 64 + ((chunk ^ ((row >> 1) & 3)) << 4);
    #pragma unroll
    for (int q = 0; q < 4; ++q)
        ldsm4(Bf[q][0][0], Bf[q][0][1], Bf[q][1][0], Bf[q][1][1],
              stb + 16384 + q * 4096 + off);
}
__device__ __forceinline__ void ldA(uint32_t stb, int s, int mt, int lane, int wm,
                                    uint32_t* A8)
{
    const int row = wm * 64 + mt * 16 + ((lane >> 3) & 1) * 8 + (lane & 7);
    const int chunk = s * 2 + ((lane >> 4) & 1);
    const uint32_t swz = row * 64 + ((chunk ^ ((row >> 1) & 3)) << 4);
    ldsm4(A8[0], A8[1], A8[2], A8[3], stb + swz);
    ldsm4(A8[4], A8[5], A8[6], A8[7], stb + 8192 + swz);
}

// grid 2048: b = (l<<3) | (rh<<2) | jg ; each CTA does 3 j-tiles x 24 k-tiles.
__global__ __launch_bounds__(256, 2) void score_kernel(
    const float* __restrict__ L, const float* __restrict__ R,
    const float* __restrict__ bn, const float* __restrict__ bg,
    const float* __restrict__ Wl)
{
    extern __shared__ __align__(1024) char smem[];
    const uint32_t sb = smem_u32(smem);
    const int t = threadIdx.x;
    const int lane = t & 31;
    const int wid = t >> 5;
    const int wm = wid >> 2, wn = wid & 3;          // 2m x 4n warps
    const int b = blockIdx.x;
    const int bl = b >> 3;                          // l
    const int rh = (b >> 2) & 1;                    // r half
    const int jg = b & 3;                           // j group (3 jt)
    const int lrh = bl * 2 + rh;
    const float* Lrow = L + (size_t)bl * 768;

    copy_tile(sb, lrh, jg * 3, 0, 0, t); cp_commit();
    copy_tile(sb, lrh, jg * 3, 1, 1, t); cp_commit();

    float scoreAcc[4][2] = {};

    for (int jl = 0; jl < 3; ++jl) {
        const int jt = jg * 3 + jl;
        float Uacc[4][2][4] = {};
        float Vacc[4][2][4] = {};
        __syncthreads();                             // previous epilogue done
        if (t < 64) {
            float* sm = (float*)(smem + OFF_META);
            int j = jt * 64 + t;
            sm[t] = bn[j]; sm[64 + t] = bg[j]; sm[128 + t] = Wl[j]; sm[192 + t] = Lrow[j];
        }
        for (int kt = 0; kt < NKT; ++kt) {
            const int i = jl * NKT + kt;
            const int st = i % 3;
            cp_wait1();
            __syncthreads();
            const uint32_t stb = sb + OFF_ST(st);

            // load ALL B fragments for this k-tile (both k16 steps) up front
            uint32_t Bf[2][4][2][2];
            ldB(stb, 0, lane, wn, Bf[0]);
            ldB(stb, 1, lane, wn, Bf[1]);

            if (i + 2 < NLOC) {
                const int i2 = i + 2;
                copy_tile(sb, lrh, jg * 3 + i2 / NKT, i2 % NKT, i2 % 3, t);
            }
            cp_commit();

            #pragma unroll
            for (int s = 0; s < 2; ++s) {
                #pragma unroll
                for (int mt = 0; mt < 4; ++mt) {
                    uint32_t A8[8];
                    ldA(stb, s, mt, lane, wm, A8);
                    #pragma unroll
                    for (int nt = 0; nt < 2; ++nt) {
                        mma16816(Uacc[mt][nt], A8,     Bf[s][0][nt]);
                        mma16816(Uacc[mt][nt], A8,     Bf[s][1][nt]);
                        mma16816(Vacc[mt][nt], A8,     Bf[s][2][nt]);
                        mma16816(Vacc[mt][nt], A8,     Bf[s][3][nt]);
                        mma16816(Uacc[mt][nt], A8 + 4, Bf[s][0][nt]);
                        mma16816(Vacc[mt][nt], A8 + 4, Bf[s][2][nt]);
                    }
                }
            }
            if (kt == NKT - 1) {
                const float* smf = (const float*)(smem + OFF_META);
                #pragma unroll
                for (int mt = 0; mt < 4; ++mt) {
                    #pragma unroll
                    for (int hf = 0; hf < 2; ++hf) {
                        const int r = rh * 128 + wm * 64 + mt * 16 + hf * 8 + (lane >> 2);
                        const float* Rr = R + (size_t)r * 768 + jt * 64;
                        float sc = scoreAcc[mt][hf];
                        #pragma unroll
                        for (int nt = 0; nt < 2; ++nt) {
                            #pragma unroll
                            for (int e = 0; e < 2; ++e) {
                                const int jl2 = wn * 16 + nt * 8 + ((lane & 3) << 1) + e;
                                const float x = fabsf(smf[192 + jl2] - Rr[jl2]);
                                const float u = Uacc[mt][nt][hf * 2 + e] + smf[jl2];
                                const float v = Vacc[mt][nt][hf * 2 + e] + smf[64 + jl2];
                                const float g = 1.f / (1.f + __expf(-v));
                                sc += (fmaxf(u, 0.f) * g + (1.f - g) * x) * smf[128 + jl2];
                            }
                        }
                        scoreAcc[mt][hf] = sc;
                    }
                }
            }
        }
    }

    float* sS = (float*)(smem + OFF_SC);
    __syncthreads();
    #pragma unroll
    for (int mt = 0; mt < 4; ++mt)
        #pragma unroll
        for (int hf = 0; hf < 2; ++hf)
            sS[(wm * 64 + mt * 16 + hf * 8 + (lane >> 2)) * 16 + wn * 4 + (lane & 3)] =
                scoreAcc[mt][hf];
    __syncthreads();
    if (t < 128) {
        float s = 0.f;
        #pragma unroll
        for (int q = 0; q < 16; ++q) s += sS[t * 16 + q];
        g_spart[jg][bl * 256 + rh * 128 + t] = s;
    }
}

// ============================ Kernel B: argmax (sums 4 j-group partials) ============================
__global__ __launch_bounds__(256) void argmax_kernel()
{
    const int b = blockIdx.x;
    const int t = threadIdx.x;
    const bool col = (b >= 256);
    const int idx = col ? (b - 256) : b;
    const int e = col ? (t * 256 + idx) : (idx * 256 + t);
    float v = g_spart[0][e] + g_spart[1][e] + g_spart[2][e] + g_spart[3][e];
    __shared__ float sv[256];
    __shared__ int   si[256];
    sv[t] = v; si[t] = t;
    __syncthreads();
    for (int s = 128; s > 0; s >>= 1) {
        if (t < s) {
            if (sv[t + s] > sv[t] || (sv[t + s] == sv[t] && si[t + s] < si[t])) {
                sv[t] = sv[t + s]; si[t] = si[t + s];
            }
        }
        __syncthreads();
    }
    if (t == 0) { if (col) g_idxR[idx] = si[0]; else g_idxL[idx] = si[0]; }
}

// ============================ Kernel C1: attribute dot scores (32 blocks) ============================
__global__ __launch_bounds__(256) void attr_s(
    const float* __restrict__ L, const float* __restrict__ R,
    const float* __restrict__ AEl, const float* __restrict__ AEr,
    const int* __restrict__ lensL, const int* __restrict__ lensR)
{
    const int b = blockIdx.x;                        // 0..31
    const int side = b >> 4;
    const int a = (b >> 2) & 3;
    const int q = b & 3;                             // token quarter
    const float* T  = side ? R : L;
    const float* AE = side ? AEr : AEl;
    const int* lens = side ? lensR : lensL;
    const int t = threadIdx.x, wid = t >> 5, lane = t & 31;

    int start = 0;
    for (int i = 0; i < a; ++i) start += lens[i];
    const int len = lens[a];
    const float* ae = AE + (size_t)a * 768;

    // 32 warps total across 4 blocks: warp (q*8 + wid) handles tokens i = that + 32k
    for (int i = q * 8 + wid; i < len; i += 32) {
        const float* tok = T + (size_t)(start + i) * 768;
        float acc = 0.f;
        #pragma unroll 8
        for (int d = lane; d < 768; d += 32) acc = fmaf(tok[d], ae[d], acc);
        #pragma unroll
        for (int o = 16; o > 0; o >>= 1) acc += __shfl_xor_sync(0xFFFFFFFF, acc, o);
        if (lane == 0) g_attrs[side * 4 + a][i] = acc;
    }
}

// ============================ Kernel C2: attribute weighted reduce (64 blocks) ============================
__global__ __launch_bounds__(256) void attr_r(
    const float* __restrict__ L, const float* __restrict__ R,
    const float* __restrict__ empty,
    const int* __restrict__ lensL, const int* __restrict__ lensR)
{
    const int b = blockIdx.x;                        // 0..63
    const int side = b >> 5;
    const int a = (b >> 3) & 3;
    const int dc = b & 7;                            // 96-wide d chunk
    const float* T  = side ? R : L;
    const float* O  = side ? L : R;
    const int*   ix = side ? g_idxR : g_idxL;
    const int* lens = side ? lensR : lensL;
    const int t = threadIdx.x, wid = t >> 5, lane = t & 31;

    int start = 0;
    for (int i = 0; i < a; ++i) start += lens[i];
    const int len = lens[a];
    float* rep = g_xent + (size_t)(side * 4 + a) * 768;
    const int d0 = dc * 96;

    if (len == 0) {
        if (t < 96) rep[d0 + t] = empty[d0 + t];
        return;
    }

    __shared__ float sw[256];
    __shared__ float red[256];
    __shared__ float racc[8][96];

    // local softmax over len scores
    float s = (t < len) ? g_attrs[side * 4 + a][t] : -1e30f;
    red[t] = s;
    for (int d = lane; d < 96; d += 32) racc[wid][d] = 0.f;
    __syncthreads();
    for (int st = 128; st > 0; st >>= 1) {
        if (t < st) red[t] = fmaxf(red[t], red[t + st]);
        __syncthreads();
    }
    const float m = red[0];
    __syncthreads();
    const float e = (t < len) ? __expf(s - m) : 0.f;
    red[t] = e;
    __syncthreads();
    for (int st = 128; st > 0; st >>= 1) {
        if (t < st) red[t] += red[t + st];
        __syncthreads();
    }
    const float z = red[0];
    __syncthreads();
    sw[t] = e / z;
    __syncthreads();

    // warp-per-token weighted abs-diff over this 96-wide chunk (coalesced)
    for (int i = wid; i < len; i += 8) {
        const int tok = start + i;
        const float w = sw[i];
        const float* Tr = T + (size_t)tok * 768 + d0;
        const float* Or = O + (size_t)ix[tok] * 768 + d0;
        #pragma unroll
        for (int d = lane; d < 96; d += 32)
            racc[wid][d] = fmaf(w, fabsf(Tr[d] - Or[d]), racc[wid][d]);
    }
    __syncthreads();
    if (t < 96) {
        float acc = 0.f;
        #pragma unroll
        for (int w = 0; w < 8; ++w) acc += racc[w][t];
        rep[d0 + t] = acc;
    }
}

// ============================ Kernel D: entity matvec partials (float4, 128 splits) ============================
__global__ __launch_bounds__(256) void ent_partial(
    const float* __restrict__ Wn, const float* __restrict__ Wg)
{
    const int j0 = (blockIdx.x * 256 + threadIdx.x) * 4;   // grid.x = 6
    const int rs = blockIdx.y;                              // 0..127
    const int i0 = rs * 48;
    float4 au = make_float4(0.f, 0.f, 0.f, 0.f);
    float4 av = make_float4(0.f, 0.f, 0.f, 0.f);
    #pragma unroll 4
    for (int i = 0; i < 48; ++i) {
        const float xi = g_xent[i0 + i];
        const float4 wn = *(const float4*)(Wn + (size_t)(i0 + i) * 6144 + j0);
        const float4 wg = *(const float4*)(Wg + (size_t)(i0 + i) * 6144 + j0);
        au.x = fmaf(xi, wn.x, au.x); au.y = fmaf(xi, wn.y, au.y);
        au.z = fmaf(xi, wn.z, au.z); au.w = fmaf(xi, wn.w, au.w);
        av.x = fmaf(xi, wg.x, av.x); av.y = fmaf(xi, wg.y, av.y);
        av.z = fmaf(xi, wg.z, av.z); av.w = fmaf(xi, wg.w, av.w);
    }
    *(float4*)(g_pu + rs * 6144 + j0) = au;
    *(float4*)(g_pv + rs * 6144 + j0) = av;
}

// ============================ Kernel E1: entity finalize partials (24 blocks) ============================
__global__ __launch_bounds__(256) void ent_final1(
    const float* __restrict__ bn, const float* __restrict__ bg,
    const float* __restrict__ Wl2)
{
    const int t = threadIdx.x;
    const int j = blockIdx.x * 256 + t;              // 6144 total
    float u = bn[j], v = bg[j];
    #pragma unroll 8
    for (int s = 0; s < 128; ++s) { u += g_pu[s * 6144 + j]; v += g_pv[s * 6144 + j]; }
    const float x = g_xent[j];
    const float g = 1.f / (1.f + __expf(-v));
    const float hw = fmaxf(u, 0.f) * g + (1.f - g) * x;
    float l0 = hw * Wl2[(size_t)j * 2 + 0];
    float l1 = hw * Wl2[(size_t)j * 2 + 1];
    __shared__ float r0[256], r1[256];
    r0[t] = l0; r1[t] = l1;
    __syncthreads();
    for (int s = 128; s > 0; s >>= 1) {
        if (t < s) { r0[t] += r0[t + s]; r1[t] += r1[t + s]; }
        __syncthreads();
    }
    if (t == 0) { g_red[blockIdx.x][0] = r0[0]; g_red[blockIdx.x][1] = r1[0]; }
}

// ============================ Kernel E2: final softmax ============================
__global__ __launch_bounds__(32) void ent_final2(
    const float* __restrict__ bl2, float* __restrict__ out)
{
    const int t = threadIdx.x;
    float l0 = (t < 24) ? g_red[t][0] : 0.f;
    float l1 = (t < 24) ? g_red[t][1] : 0.f;
    #pragma unroll
    for (int o = 16; o > 0; o >>= 1) {
        l0 += __shfl_xor_sync(0xFFFFFFFF, l0, o);
        l1 += __shfl_xor_sync(0xFFFFFFFF, l1, o);
    }
    if (t == 0) {
        const float a = l0 + bl2[0];
        const float b = l1 + bl2[1];
        const float m = fmaxf(a, b);
        const float ea = __expf(a - m), eb = __expf(b - m);
        const float inv = 1.f / (ea + eb);
        out[0] = ea * inv;
        out[1] = eb * inv;
    }
}

// ============================ launcher ============================
extern "C" void kernel_launch(void* const* d_in, const int* in_sizes, int n_in,
                              void* d_out, int out_size)
{
    const float* left_emb   = (const float*)d_in[0];
    const float* right_emb  = (const float*)d_in[1];
    const float* Wn_tok     = (const float*)d_in[2];
    const float* bn_tok     = (const float*)d_in[3];
    const float* Wg_tok     = (const float*)d_in[4];
    const float* bg_tok     = (const float*)d_in[5];
    const float* W_lin_tok  = (const float*)d_in[6];
    const float* attr_l     = (const float*)d_in[8];
    const float* attr_r_e   = (const float*)d_in[9];
    const float* Wn_ent     = (const float*)d_in[10];
    const float* bn_ent     = (const float*)d_in[11];
    const float* Wg_ent     = (const float*)d_in[12];
    const float* bg_ent     = (const float*)d_in[13];
    const float* W_lin_ent  = (const float*)d_in[14];
    const float* b_lin_ent  = (const float*)d_in[15];
    const float* empty_attr = (const float*)d_in[16];
    const int*   lensL      = (const int*)d_in[17];
    const int*   lensR      = (const int*)d_in[18];
    float* out = (float*)d_out;

    cudaFuncSetAttribute(score_kernel, cudaFuncAttributeMaxDynamicSharedMemorySize, SMEM_BYTES);

    prep_all<<<2624, 256>>>(Wn_tok, Wg_tok, left_emb, right_emb);   // launch 0
    score_kernel<<<2048, 256, SMEM_BYTES>>>(left_emb, right_emb, bn_tok, bg_tok, W_lin_tok); // 1
    argmax_kernel<<<512, 256>>>();                                  // launch 2
    attr_s<<<32, 256>>>(left_emb, right_emb, attr_l, attr_r_e,
                        lensL, lensR);                              // launch 3 (profiled)
    attr_r<<<64, 256>>>(left_emb, right_emb, empty_attr, lensL, lensR);
    dim3 gridD(6, 128);
    ent_partial<<<gridD, 256>>>(Wn_ent, Wg_ent);
    ent_final1<<<24, 256>>>(bn_ent, bg_ent, W_lin_ent);
    ent_final2<<<1, 32>>>(b_lin_ent, out);
}

// round 17
// speedup vs baseline: 1.0681x; 1.0032x over previous
#include <cuda_runtime.h>
#include <cuda_bf16.h>
#include <math.h>
#include <stdint.h>

// ============================ device scratch ============================
__device__ float g_spart[4][256 * 256];
__device__ int   g_idxL[256];
__device__ int   g_idxR[256];
__device__ float g_xent[6144];
__device__ float g_attrs[8][256];
__device__ float g_pu[128 * 6144];
__device__ float g_pv[128 * 6144];
__device__ float g_red[24][2];
// W tiles: [q(4: nH,nL,gH,gL)][jt(12)][kt(24)] of 64j x 32k bf16 (4096B)
__device__ __align__(16) __nv_bfloat16 g_Wprep[4 * 12 * 24 * 2048];
// A tiles: [l(256)][rh(2)][kt(24)]: hi 8KB + lo 8KB (128r x 32k each)
__device__ __align__(16) __nv_bfloat16 g_Aprep[(size_t)256 * 2 * 24 * 8192];

#define NJT 12
#define NKT 24
#define NLOC 72          /* 3 jt x 24 kt per CTA */

// SMEM: 3 stages x 32KB (A hi 8K, A lo 8K, W 16K), meta 1KB, reduce 8KB
#define OFF_ST(st)  ((st) * 32768)
#define OFF_META    98304
#define OFF_SC      99328
#define SMEM_BYTES  107520

// ============================ helpers ============================
__device__ __forceinline__ uint32_t smem_u32(const void* p) {
    uint32_t a;
    asm("{ .reg .u64 t; cvta.to.shared.u64 t, %1; cvt.u32.u64 %0, t; }" : "=r"(a) : "l"(p));
    return a;
}
__device__ __forceinline__ void cp16(uint32_t s, const void* g) {
    asm volatile("cp.async.cg.shared.global [%0], [%1], 16;" :: "r"(s), "l"(g));
}
__device__ __forceinline__ void cp_commit() { asm volatile("cp.async.commit_group;"); }
__device__ __forceinline__ void cp_wait1()  { asm volatile("cp.async.wait_group 1;" ::: "memory"); }
__device__ __forceinline__ void ldsm4(uint32_t& r0, uint32_t& r1, uint32_t& r2, uint32_t& r3,
                                      uint32_t a) {
    asm volatile("ldmatrix.sync.aligned.m8n8.x4.shared.b16 {%0,%1,%2,%3}, [%4];"
                 : "=r"(r0), "=r"(r1), "=r"(r2), "=r"(r3) : "r"(a));
}
__device__ __forceinline__ void mma16816(float* d, const uint32_t* a, const uint32_t* b) {
    asm volatile("mma.sync.aligned.m16n8k16.row.col.f32.bf16.bf16.f32 "
                 "{%0,%1,%2,%3},{%4,%5,%6,%7},{%8,%9},{%0,%1,%2,%3};"
                 : "+f"(d[0]), "+f"(d[1]), "+f"(d[2]), "+f"(d[3])
                 : "r"(a[0]), "r"(a[1]), "r"(a[2]), "r"(a[3]), "r"(b[0]), "r"(b[1]));
}
__device__ __forceinline__ void split2(float d0, float d1, uint32_t& hi, uint32_t& lo) {
    union { __nv_bfloat162 b; uint32_t u; } ch, cl;
    ch.b = __floats2bfloat162_rn(d0, d1);
    float f0 = __uint_as_float(ch.u << 16);
    float f1 = __uint_as_float(ch.u & 0xFFFF0000u);
    cl.b = __floats2bfloat162_rn(d0 - f0, d1 - f1);
    hi = ch.u; lo = cl.u;
}

// ============================ Kernel P: merged weight prep + A prebuild ============================
__global__ __launch_bounds__(256) void prep_all(const float* __restrict__ Wn,
                                                const float* __restrict__ Wg,
                                                const float* __restrict__ L,
                                                const float* __restrict__ R)
{
    const int t = threadIdx.x;
    if (blockIdx.x < 576) {
        int tid = blockIdx.x * 256 + t;             // 147456 = 2*96*768
        int mat = tid / 73728;
        int rem = tid - mat * 73728;
        int kc  = rem / 768;                         // 0..95, k0 = kc*8
        int j   = rem - kc * 768;
        const float* W = mat ? Wg : Wn;
        int k0 = kc * 8;
        uint32_t hi[4], lo[4];
        #pragma unroll
        for (int p = 0; p < 4; ++p)
            split2(W[(size_t)(k0 + 2 * p) * 768 + j], W[(size_t)(k0 + 2 * p + 1) * 768 + j],
                   hi[p], lo[p]);
        int kt = kc >> 2, c = kc & 3;
        int jt = j >> 6, row = j & 63;
        int off = row * 64 + ((c ^ ((row >> 1) & 3)) << 4);
        char* bh = (char*)g_Wprep + (size_t)(((mat * 2 + 0) * NJT + jt) * NKT + kt) * 4096 + off;
        char* bl = (char*)g_Wprep + (size_t)(((mat * 2 + 1) * NJT + jt) * NKT + kt) * 4096 + off;
        *(uint4*)bh = make_uint4(hi[0], hi[1], hi[2], hi[3]);
        *(uint4*)bl = make_uint4(lo[0], lo[1], lo[2], lo[3]);
    } else {
        const int bb = blockIdx.x - 576;
        const int l = bb >> 3;
        const int ktg = bb & 7;                     // 3 kt per block
        const int rh = t >> 7, row = t & 127;
        const float* Lrow = L + (size_t)l * 768;
        #pragma unroll
        for (int kk = 0; kk < 3; ++kk) {
            const int kt = ktg * 3 + kk;
            const int k0 = kt * 32;
            const float* Rr = R + (size_t)t * 768 + k0;
            const float* Lr = Lrow + k0;
            char* base = (char*)g_Aprep + (size_t)((l * 2 + rh) * 24 + kt) * 16384;
            #pragma unroll
            for (int c = 0; c < 4; ++c) {
                float4 r0 = *(const float4*)(Rr + c * 8);
                float4 r1 = *(const float4*)(Rr + c * 8 + 4);
                float4 l0 = *(const float4*)(Lr + c * 8);
                float4 l1 = *(const float4*)(Lr + c * 8 + 4);
                uint32_t h0, h1, h2, h3, e0, e1, e2, e3;
                split2(fabsf(l0.x - r0.x), fabsf(l0.y - r0.y), h0, e0);
                split2(fabsf(l0.z - r0.z), fabsf(l0.w - r0.w), h1, e1);
                split2(fabsf(l1.x - r1.x), fabsf(l1.y - r1.y), h2, e2);
                split2(fabsf(l1.z - r1.z), fabsf(l1.w - r1.w), h3, e3);
                const int off = row * 64 + ((c ^ ((row >> 1) & 3)) << 4);
                *(uint4*)(base + off) = make_uint4(h0, h1, h2, h3);
                *(uint4*)(base + 8192 + off) = make_uint4(e0, e1, e2, e3);
            }
        }
    }
}

// ============================ Kernel A: HMMA score GEMM ============================
__device__ __forceinline__ void copy_tile(uint32_t sb, int lrh, int jt, int kt,
                                          int st, int t)
{
    const char* ga = (const char*)g_Aprep + (size_t)(lrh * 24 + kt) * 16384;
    #pragma unroll
    for (int q = 0; q < 4; ++q)
        cp16(sb + OFF_ST(st) + q * 4096 + t * 16, ga + q * 4096 + t * 16);
    #pragma unroll
    for (int q = 0; q < 4; ++q)
        cp16(sb + OFF_ST(st) + 16384 + q * 4096 + t * 16,
             (const char*)g_Wprep + (size_t)((q * NJT + jt) * NKT + kt) * 4096 + t * 16);
}

__device__ __forceinline__ void ldB(uint32_t stb, int s, int lane, int wn,
                                    uint32_t Bf[4][2][2])
{
    const int row = wn * 16 + ((lane >> 4) & 1) * 8 + (lane & 7);
    const int chunk = s * 2 + ((lane >> 3) & 1);
    const uint32_t off = row * 64 + ((chunk ^ ((row >> 1) & 3)) << 4);
    #pragma unroll
    for (int q = 0; q < 4; ++q)
        ldsm4(Bf[q][0][0], Bf[q][0][1], Bf[q][1][0], Bf[q][1][1],
              stb + 16384 + q * 4096 + off);
}
__device__ __forceinline__ void ldA(uint32_t stb, int s, int mt, int lane, int wm,
                                    uint32_t* A8)
{
    const int row = wm * 64 + mt * 16 + ((lane >> 3) & 1) * 8 + (lane & 7);
    const int chunk = s * 2 + ((lane >> 4) & 1);
    const uint32_t swz = row * 64 + ((chunk ^ ((row >> 1) & 3)) << 4);
    ldsm4(A8[0], A8[1], A8[2], A8[3], stb + swz);
    ldsm4(A8[4], A8[5], A8[6], A8[7], stb + 8192 + swz);
}

// grid 2048: b = (l<<3) | (rh<<2) | jg ; each CTA does 3 j-tiles x 24 k-tiles.
__global__ __launch_bounds__(256, 2) void score_kernel(
    const float* __restrict__ L, const float* __restrict__ R,
    const float* __restrict__ bn, const float* __restrict__ bg,
    const float* __restrict__ Wl)
{
    extern __shared__ __align__(1024) char smem[];
    const uint32_t sb = smem_u32(smem);
    const int t = threadIdx.x;
    const int lane = t & 31;
    const int wid = t >> 5;
    const int wm = wid >> 2, wn = wid & 3;          // 2m x 4n warps
    const int b = blockIdx.x;
    const int bl = b >> 3;                          // l
    const int rh = (b >> 2) & 1;                    // r half
    const int jg = b & 3;                           // j group (3 jt)
    const int lrh = bl * 2 + rh;
    const float* Lrow = L + (size_t)bl * 768;

    copy_tile(sb, lrh, jg * 3, 0, 0, t); cp_commit();
    copy_tile(sb, lrh, jg * 3, 1, 1, t); cp_commit();

    float scoreAcc[4][2] = {};

    for (int jl = 0; jl < 3; ++jl) {
        const int jt = jg * 3 + jl;
        float Uacc[4][2][4] = {};
        float Vacc[4][2][4] = {};
        __syncthreads();                             // previous epilogue done
        if (t < 64) {
            float* sm = (float*)(smem + OFF_META);
            int j = jt * 64 + t;
            sm[t] = bn[j]; sm[64 + t] = bg[j]; sm[128 + t] = Wl[j]; sm[192 + t] = Lrow[j];
        }
        for (int kt = 0; kt < NKT; ++kt) {
            const int i = jl * NKT + kt;
            const int st = i % 3;
            cp_wait1();
            __syncthreads();
            const uint32_t stb = sb + OFF_ST(st);

            // load ALL B fragments for this k-tile (both k16 steps) up front
            uint32_t Bf[2][4][2][2];
            ldB(stb, 0, lane, wn, Bf[0]);
            ldB(stb, 1, lane, wn, Bf[1]);

            if (i + 2 < NLOC) {
                const int i2 = i + 2;
                copy_tile(sb, lrh, jg * 3 + i2 / NKT, i2 % NKT, i2 % 3, t);
            }
            cp_commit();

            #pragma unroll
            for (int s = 0; s < 2; ++s) {
                #pragma unroll
                for (int mt = 0; mt < 4; ++mt) {
                    uint32_t A8[8];
                    ldA(stb, s, mt, lane, wm, A8);
                    #pragma unroll
                    for (int nt = 0; nt < 2; ++nt) {
                        mma16816(Uacc[mt][nt], A8,     Bf[s][0][nt]);
                        mma16816(Uacc[mt][nt], A8,     Bf[s][1][nt]);
                        mma16816(Vacc[mt][nt], A8,     Bf[s][2][nt]);
                        mma16816(Vacc[mt][nt], A8,     Bf[s][3][nt]);
                        mma16816(Uacc[mt][nt], A8 + 4, Bf[s][0][nt]);
                        mma16816(Vacc[mt][nt], A8 + 4, Bf[s][2][nt]);
                    }
                }
            }
            if (kt == NKT - 1) {
                const float* smf = (const float*)(smem + OFF_META);
                #pragma unroll
                for (int mt = 0; mt < 4; ++mt) {
                    #pragma unroll
                    for (int hf = 0; hf < 2; ++hf) {
                        const int r = rh * 128 + wm * 64 + mt * 16 + hf * 8 + (lane >> 2);
                        const float* Rr = R + (size_t)r * 768 + jt * 64;
                        float sc = scoreAcc[mt][hf];
                        #pragma unroll
                        for (int nt = 0; nt < 2; ++nt) {
                            #pragma unroll
                            for (int e = 0; e < 2; ++e) {
                                const int jl2 = wn * 16 + nt * 8 + ((lane & 3) << 1) + e;
                                const float x = fabsf(smf[192 + jl2] - Rr[jl2]);
                                const float u = Uacc[mt][nt][hf * 2 + e] + smf[jl2];
                                const float v = Vacc[mt][nt][hf * 2 + e] + smf[64 + jl2];
                                const float g = 1.f / (1.f + __expf(-v));
                                sc += (fmaxf(u, 0.f) * g + (1.f - g) * x) * smf[128 + jl2];
                            }
                        }
                        scoreAcc[mt][hf] = sc;
                    }
                }
            }
        }
    }

    float* sS = (float*)(smem + OFF_SC);
    __syncthreads();
    #pragma unroll
    for (int mt = 0; mt < 4; ++mt)
        #pragma unroll
        for (int hf = 0; hf < 2; ++hf)
            sS[(wm * 64 + mt * 16 + hf * 8 + (lane >> 2)) * 16 + wn * 4 + (lane & 3)] =
                scoreAcc[mt][hf];
    __syncthreads();
    if (t < 128) {
        float s = 0.f;
        #pragma unroll
        for (int q = 0; q < 16; ++q) s += sS[t * 16 + q];
        g_spart[jg][bl * 256 + rh * 128 + t] = s;
    }
}

// ============================ Kernel B: argmax + attr scores (544 blocks) ============================
// Blocks 0..511: argmax rows/cols (sums 4 j-group partials).
// Blocks 512..543: attr dot scores (independent of argmax).
__global__ __launch_bounds__(256) void argmax_attrs(
    const float* __restrict__ L, const float* __restrict__ R,
    const float* __restrict__ AEl, const float* __restrict__ AEr,
    const int* __restrict__ lensL, const int* __restrict__ lensR)
{
    const int t = threadIdx.x;
    if (blockIdx.x < 512) {
        const int b = blockIdx.x;
        const bool col = (b >= 256);
        const int idx = col ? (b - 256) : b;
        const int e = col ? (t * 256 + idx) : (idx * 256 + t);
        float v = g_spart[0][e] + g_spart[1][e] + g_spart[2][e] + g_spart[3][e];
        __shared__ float sv[256];
        __shared__ int   si[256];
        sv[t] = v; si[t] = t;
        __syncthreads();
        for (int s = 128; s > 0; s >>= 1) {
            if (t < s) {
                if (sv[t + s] > sv[t] || (sv[t + s] == sv[t] && si[t + s] < si[t])) {
                    sv[t] = sv[t + s]; si[t] = si[t + s];
                }
            }
            __syncthreads();
        }
        if (t == 0) { if (col) g_idxR[idx] = si[0]; else g_idxL[idx] = si[0]; }
    } else {
        const int b = blockIdx.x - 512;              // 0..31
        const int side = b >> 4;
        const int a = (b >> 2) & 3;
        const int q = b & 3;
        const float* T  = side ? R : L;
        const float* AE = side ? AEr : AEl;
        const int* lens = side ? lensR : lensL;
        const int wid = t >> 5, lane = t & 31;

        int start = 0;
        for (int i = 0; i < a; ++i) start += lens[i];
        const int len = lens[a];
        const float* ae = AE + (size_t)a * 768;

        for (int i = q * 8 + wid; i < len; i += 32) {
            const float* tok = T + (size_t)(start + i) * 768;
            float acc = 0.f;
            #pragma unroll 8
            for (int d = lane; d < 768; d += 32) acc = fmaf(tok[d], ae[d], acc);
            #pragma unroll
            for (int o = 16; o > 0; o >>= 1) acc += __shfl_xor_sync(0xFFFFFFFF, acc, o);
            if (lane == 0) g_attrs[side * 4 + a][i] = acc;
        }
    }
}

// ============================ Kernel C2: attribute weighted reduce (64 blocks) ============================
__global__ __launch_bounds__(256) void attr_r(
    const float* __restrict__ L, const float* __restrict__ R,
    const float* __restrict__ empty,
    const int* __restrict__ lensL, const int* __restrict__ lensR)
{
    const int b = blockIdx.x;                        // 0..63
    const int side = b >> 5;
    const int a = (b >> 3) & 3;
    const int dc = b & 7;                            // 96-wide d chunk
    const float* T  = side ? R : L;
    const float* O  = side ? L : R;
    const int*   ix = side ? g_idxR : g_idxL;
    const int* lens = side ? lensR : lensL;
    const int t = threadIdx.x, wid = t >> 5, lane = t & 31;

    int start = 0;
    for (int i = 0; i < a; ++i) start += lens[i];
    const int len = lens[a];
    float* rep = g_xent + (size_t)(side * 4 + a) * 768;
    const int d0 = dc * 96;

    if (len == 0) {
        if (t < 96) rep[d0 + t] = empty[d0 + t];
        return;
    }

    __shared__ float sw[256];
    __shared__ float red[256];
    __shared__ float racc[8][96];

    float s = (t < len) ? g_attrs[side * 4 + a][t] : -1e30f;
    red[t] = s;
    for (int d = lane; d < 96; d += 32) racc[wid][d] = 0.f;
    __syncthreads();
    for (int st = 128; st > 0; st >>= 1) {
        if (t < st) red[t] = fmaxf(red[t], red[t + st]);
        __syncthreads();
    }
    const float m = red[0];
    __syncthreads();
    const float e = (t < len) ? __expf(s - m) : 0.f;
    red[t] = e;
    __syncthreads();
    for (int st = 128; st > 0; st >>= 1) {
        if (t < st) red[t] += red[t + st];
        __syncthreads();
    }
    const float z = red[0];
    __syncthreads();
    sw[t] = e / z;
    __syncthreads();

    for (int i = wid; i < len; i += 8) {
        const int tok = start + i;
        const float w = sw[i];
        const float* Tr = T + (size_t)tok * 768 + d0;
        const float* Or = O + (size_t)ix[tok] * 768 + d0;
        #pragma unroll
        for (int d = lane; d < 96; d += 32)
            racc[wid][d] = fmaf(w, fabsf(Tr[d] - Or[d]), racc[wid][d]);
    }
    __syncthreads();
    if (t < 96) {
        float acc = 0.f;
        #pragma unroll
        for (int w = 0; w < 8; ++w) acc += racc[w][t];
        rep[d0 + t] = acc;
    }
}

// ============================ Kernel D: entity matvec partials (float4, 128 splits) ============================
__global__ __launch_bounds__(256) void ent_partial(
    const float* __restrict__ Wn, const float* __restrict__ Wg)
{
    const int j0 = (blockIdx.x * 256 + threadIdx.x) * 4;   // grid.x = 6
    const int rs = blockIdx.y;                              // 0..127
    const int i0 = rs * 48;
    float4 au = make_float4(0.f, 0.f, 0.f, 0.f);
    float4 av = make_float4(0.f, 0.f, 0.f, 0.f);
    #pragma unroll 4
    for (int i = 0; i < 48; ++i) {
        const float xi = g_xent[i0 + i];
        const float4 wn = *(const float4*)(Wn + (size_t)(i0 + i) * 6144 + j0);
        const float4 wg = *(const float4*)(Wg + (size_t)(i0 + i) * 6144 + j0);
        au.x = fmaf(xi, wn.x, au.x); au.y = fmaf(xi, wn.y, au.y);
        au.z = fmaf(xi, wn.z, au.z); au.w = fmaf(xi, wn.w, au.w);
        av.x = fmaf(xi, wg.x, av.x); av.y = fmaf(xi, wg.y, av.y);
        av.z = fmaf(xi, wg.z, av.z); av.w = fmaf(xi, wg.w, av.w);
    }
    *(float4*)(g_pu + rs * 6144 + j0) = au;
    *(float4*)(g_pv + rs * 6144 + j0) = av;
}

// ============================ Kernel E1: entity finalize partials (24 blocks) ============================
__global__ __launch_bounds__(256) void ent_final1(
    const float* __restrict__ bn, const float* __restrict__ bg,
    const float* __restrict__ Wl2)
{
    const int t = threadIdx.x;
    const int j = blockIdx.x * 256 + t;              // 6144 total
    float u = bn[j], v = bg[j];
    #pragma unroll 8
    for (int s = 0; s < 128; ++s) { u += g_pu[s * 6144 + j]; v += g_pv[s * 6144 + j]; }
    const float x = g_xent[j];
    const float g = 1.f / (1.f + __expf(-v));
    const float hw = fmaxf(u, 0.f) * g + (1.f - g) * x;
    float l0 = hw * Wl2[(size_t)j * 2 + 0];
    float l1 = hw * Wl2[(size_t)j * 2 + 1];
    __shared__ float r0[256], r1[256];
    r0[t] = l0; r1[t] = l1;
    __syncthreads();
    for (int s = 128; s > 0; s >>= 1) {
        if (t < s) { r0[t] += r0[t + s]; r1[t] += r1[t + s]; }
        __syncthreads();
    }
    if (t == 0) { g_red[blockIdx.x][0] = r0[0]; g_red[blockIdx.x][1] = r1[0]; }
}

// ============================ Kernel E2: final softmax ============================
__global__ __launch_bounds__(32) void ent_final2(
    const float* __restrict__ bl2, float* __restrict__ out)
{
    const int t = threadIdx.x;
    float l0 = (t < 24) ? g_red[t][0] : 0.f;
    float l1 = (t < 24) ? g_red[t][1] : 0.f;
    #pragma unroll
    for (int o = 16; o > 0; o >>= 1) {
        l0 += __shfl_xor_sync(0xFFFFFFFF, l0, o);
        l1 += __shfl_xor_sync(0xFFFFFFFF, l1, o);
    }
    if (t == 0) {
        const float a = l0 + bl2[0];
        const float b = l1 + bl2[1];
        const float m = fmaxf(a, b);
        const float ea = __expf(a - m), eb = __expf(b - m);
        const float inv = 1.f / (ea + eb);
        out[0] = ea * inv;
        out[1] = eb * inv;
    }
}

// ============================ launcher ============================
extern "C" void kernel_launch(void* const* d_in, const int* in_sizes, int n_in,
                              void* d_out, int out_size)
{
    const float* left_emb   = (const float*)d_in[0];
    const float* right_emb  = (const float*)d_in[1];
    const float* Wn_tok     = (const float*)d_in[2];
    const float* bn_tok     = (const float*)d_in[3];
    const float* Wg_tok     = (const float*)d_in[4];
    const float* bg_tok     = (const float*)d_in[5];
    const float* W_lin_tok  = (const float*)d_in[6];
    const float* attr_l     = (const float*)d_in[8];
    const float* attr_r_e   = (const float*)d_in[9];
    const float* Wn_ent     = (const float*)d_in[10];
    const float* bn_ent     = (const float*)d_in[11];
    const float* Wg_ent     = (const float*)d_in[12];
    const float* bg_ent     = (const float*)d_in[13];
    const float* W_lin_ent  = (const float*)d_in[14];
    const float* b_lin_ent  = (const float*)d_in[15];
    const float* empty_attr = (const float*)d_in[16];
    const int*   lensL      = (const int*)d_in[17];
    const int*   lensR      = (const int*)d_in[18];
    float* out = (float*)d_out;

    cudaFuncSetAttribute(score_kernel, cudaFuncAttributeMaxDynamicSharedMemorySize, SMEM_BYTES);

    prep_all<<<2624, 256>>>(Wn_tok, Wg_tok, left_emb, right_emb);   // launch 0
    score_kernel<<<2048, 256, SMEM_BYTES>>>(left_emb, right_emb, bn_tok, bg_tok, W_lin_tok); // 1
    argmax_attrs<<<544, 256>>>(left_emb, right_emb, attr_l, attr_r_e,
                               lensL, lensR);                       // launch 2
    attr_r<<<64, 256>>>(left_emb, right_emb, empty_attr, lensL, lensR); // launch 3 (profiled)
    dim3 gridD(6, 128);
    ent_partial<<<gridD, 256>>>(Wn_ent, Wg_ent);
    ent_final1<<<24, 256>>>(bn_ent, bg_ent, W_lin_ent);
    ent_final2<<<1, 32>>>(b_lin_ent, out);
}